// round 15
// baseline (speedup 1.0000x reference)
#include <cuda_runtime.h>
#include <cuda_fp16.h>
#include <math.h>
#include <stdint.h>

#define TOKENS 4096
#define DMODEL 1024
#define DINNER 2048
#define DSTATE 16
#define SEQL   2048

// Scratch (static device globals — no runtime allocation allowed)
__device__ __align__(256) float  g_xz [TOKENS * 2 * DINNER];  // GEMM1 out: xi-preconv | z
__device__ __align__(256) float  g_xi [TOKENS * DINNER];      // conv+silu output (fp32)
__device__ __align__(256) float  g_dbc[TOKENS * 33];
__device__ __align__(256) float  g_dbcp[16][TOKENS * 33];
__device__ __align__(256) __half g_xh [TOKENS * DMODEL];      // half x
__device__ __align__(256) __half g_wh [2 * DINNER * DMODEL];  // half W_in
__device__ __align__(256) __half g_woh[DMODEL * DINNER];      // half W_out
__device__ __align__(256) __half g_yh [TOKENS * DINNER];      // half scan output
__device__ int g_cntx[TOKENS / 64];                           // zero-init; self-resetting

// ---------------------------------------------------------------------------
__device__ __forceinline__ void cp_async16(void* smem_dst, const void* gmem_src) {
    uint32_t s = (uint32_t)__cvta_generic_to_shared(smem_dst);
    asm volatile("cp.async.cg.shared.global [%0], [%1], 16;" :: "r"(s), "l"(gmem_src));
}

__device__ __forceinline__ void mma_f16(float* c, const uint32_t* a, const uint32_t* b) {
    asm volatile(
        "mma.sync.aligned.m16n8k16.row.col.f32.f16.f16.f32 "
        "{%0,%1,%2,%3}, {%4,%5,%6,%7}, {%8,%9}, {%0,%1,%2,%3};"
        : "+f"(c[0]), "+f"(c[1]), "+f"(c[2]), "+f"(c[3])
        : "r"(a[0]), "r"(a[1]), "r"(a[2]), "r"(a[3]), "r"(b[0]), "r"(b[1]));
}

__device__ __forceinline__ void ldsm_x4(uint32_t& r0, uint32_t& r1, uint32_t& r2,
                                        uint32_t& r3, uint32_t saddr) {
    asm volatile("ldmatrix.sync.aligned.m8n8.x4.shared.b16 {%0,%1,%2,%3}, [%4];"
        : "=r"(r0), "=r"(r1), "=r"(r2), "=r"(r3) : "r"(saddr));
}

// ---------------------------------------------------------------------------
// FP16 mma.sync GEMM (unchanged): BM=BN=128, BK=64, 3-stage, 2 CTAs/SM.
// ---------------------------------------------------------------------------
#define BM 128
#define BN 128
#define BK 64
#define STRH 72
#define A_HALFS (BM * STRH)
#define B_HALFS (BN * STRH)
#define STG_HALFS (A_HALFS + B_HALFS)
#define GEMM_SMEM (3 * STG_HALFS * 2)        // 110592 B

__global__ void __launch_bounds__(256, 2)
h_gemm_nt(const __half* __restrict__ A, const __half* __restrict__ B,
          float* __restrict__ C, int M, int N, int K) {
    extern __shared__ __half sh[];
    constexpr int WN = 32;
    constexpr int NFN = 4;
    constexpr int NPAIR = 2;

    const int tid  = threadIdx.x;
    const int wid  = tid >> 5;
    const int lane = tid & 31;
    const int gid  = lane >> 2;
    const int t4   = lane & 3;
    const int wm   = wid & 1;
    const int wn   = wid >> 1;
    const int row0 = blockIdx.y * BM;
    const int col0 = blockIdx.x * BN;

    const uint32_t sbase = (uint32_t)__cvta_generic_to_shared(sh);

    const int a_row  = wm * 64 + (lane & 15);
    const int a_colh = (lane >> 4) * 8;
    const int b_row  = (lane & 7) + ((lane >> 4) * 8);
    const int b_colh = ((lane >> 3) & 1) * 8;

    const int lrow = tid >> 3;
    const int lchk = (tid & 7) * 8;

    float acc[4][NFN][4] = {};
    const int niter = K / BK;

    auto load_stage = [&](int stage, int k0) {
        __half* Sa = sh + stage * STG_HALFS;
        __half* Sb = Sa + A_HALFS;
#pragma unroll
        for (int i = 0; i < BM / 32; i++) {
            int r = lrow + i * 32;
            cp_async16(&Sa[r * STRH + lchk], A + (size_t)(row0 + r) * K + k0 + lchk);
        }
#pragma unroll
        for (int i = 0; i < BN / 32; i++) {
            int r = lrow + i * 32;
            cp_async16(&Sb[r * STRH + lchk], B + (size_t)(col0 + r) * K + k0 + lchk);
        }
    };

    load_stage(0, 0);
    asm volatile("cp.async.commit_group;");
    if (niter > 1) load_stage(1, BK);
    asm volatile("cp.async.commit_group;");

    int s = 0;
    for (int it = 0; it < niter; it++) {
        asm volatile("cp.async.wait_group 1;");
        __syncthreads();

        if (it + 2 < niter) load_stage((it + 2) % 3, (it + 2) * BK);
        asm volatile("cp.async.commit_group;");

        const uint32_t sA = sbase + (uint32_t)(s * STG_HALFS) * 2;
        const uint32_t sB = sA + A_HALFS * 2;
#pragma unroll
        for (int kk = 0; kk < BK / 16; kk++) {
            const int kb = kk * 16;
            uint32_t af[4][4], bf[NFN][2];
#pragma unroll
            for (int fm = 0; fm < 4; fm++)
                ldsm_x4(af[fm][0], af[fm][1], af[fm][2], af[fm][3],
                        sA + (uint32_t)((a_row + fm * 16) * STRH + kb + a_colh) * 2);
#pragma unroll
            for (int p = 0; p < NPAIR; p++)
                ldsm_x4(bf[2 * p][0], bf[2 * p][1], bf[2 * p + 1][0], bf[2 * p + 1][1],
                        sB + (uint32_t)((wn * WN + p * 16 + b_row) * STRH + kb + b_colh) * 2);
#pragma unroll
            for (int fm = 0; fm < 4; fm++)
#pragma unroll
                for (int fn = 0; fn < NFN; fn++)
                    mma_f16(acc[fm][fn], af[fm], bf[fn]);
        }
        s = (s + 1) % 3;
    }

#pragma unroll
    for (int fm = 0; fm < 4; fm++) {
        int r = row0 + wm * 64 + fm * 16 + gid;
#pragma unroll
        for (int fn = 0; fn < NFN; fn++) {
            int cbase = col0 + wn * WN + fn * 8 + t4 * 2;
            float2* p0 = (float2*)&C[(size_t)r * N + cbase];
            float2* p1 = (float2*)&C[(size_t)(r + 8) * N + cbase];
            *p0 = make_float2(acc[fm][fn][0], acc[fm][fn][1]);
            *p1 = make_float2(acc[fm][fn][2], acc[fm][fn][3]);
        }
    }
}

// ---------------------------------------------------------------------------
// fp32->fp16 conversion
// ---------------------------------------------------------------------------
#define N4_X  (TOKENS * DMODEL / 4)
#define N4_WI (2 * DINNER * DMODEL / 4)
#define N4_WO (DMODEL * DINNER / 4)

__global__ void cvt_xw_k(const float* __restrict__ x, const float* __restrict__ Wi) {
    int i = blockIdx.x * blockDim.x + threadIdx.x;
    const float* src; __half* dst; int off;
    if (i < N4_X)               { src = x;  dst = g_xh; off = i; }
    else if (i < N4_X + N4_WI)  { src = Wi; dst = g_wh; off = i - N4_X; }
    else return;
    float4 v = ((const float4*)src)[off];
    __half2 h0 = __float22half2_rn(make_float2(v.x, v.y));
    __half2 h1 = __float22half2_rn(make_float2(v.z, v.w));
    ((uint2*)dst)[off] = make_uint2(*(uint32_t*)&h0, *(uint32_t*)&h1);
}

__global__ void cvt_wo_k(const float* __restrict__ Wo) {
    int i = blockIdx.x * blockDim.x + threadIdx.x;
    if (i >= N4_WO) return;
    float4 v = ((const float4*)Wo)[i];
    __half2 h0 = __float22half2_rn(make_float2(v.x, v.y));
    __half2 h1 = __float22half2_rn(make_float2(v.z, v.w));
    ((uint2*)g_woh)[i] = make_uint2(*(uint32_t*)&h0, *(uint32_t*)&h1);
}

// ---------------------------------------------------------------------------
// Fused conv+SiLU + x_dbl partials + LAST-BLOCK reduce (threadfence/counter).
// Reduce order is fixed p=0..15 -> bit-identical to the old reduce kernel.
// Counters self-reset -> safe across graph replays.
// ---------------------------------------------------------------------------
__global__ void __launch_bounds__(264, 5)
xdbl_conv_k(const float* __restrict__ Wx,
            const float* __restrict__ cw,
            const float* __restrict__ cb) {
    __shared__ float Sxz[67][36];
    __shared__ float Xs [64][33];
    __shared__ float Ws [33][33];
    __shared__ float Scw[32][5];
    __shared__ int sOld;
    const int tx = threadIdx.x, ty = threadIdx.y;   // (33,8)
    const int tid = ty * 33 + tx;
    const int tok0 = blockIdx.x * 64;
    const int kbase = blockIdx.y * 128;             // split-K 16
    const bool halo_ok = (tok0 & (SEQL - 1)) != 0;

    float acc[8] = {};

    for (int kc = 0; kc < 4; kc++) {
        const int k0 = kbase + kc * 32;
        for (int i = tid; i < 33 * 32; i += 264) {
            int e = i >> 5, kk = i & 31;
            Ws[e][kk] = Wx[(size_t)e * DINNER + k0 + kk];
        }
        if (tid < 32 * 5) {
            int kk = tid / 5, j = tid - kk * 5;
            Scw[kk][j] = (j < 4) ? cw[(k0 + kk) * 4 + j] : cb[k0 + kk];
        }
        for (int i = tid; i < 67 * 8; i += 264) {
            int row = i >> 3, c4 = (i & 7) * 4;
            float4 v = make_float4(0.f, 0.f, 0.f, 0.f);
            if (row >= 3 || halo_ok)
                v = *(const float4*)&g_xz[(size_t)(tok0 - 3 + row) * (2 * DINNER) + k0 + c4];
            *(float4*)&Sxz[row][c4] = v;
        }
        __syncthreads();

        for (int i = tid; i < 64 * 32; i += 264) {
            int tt = i >> 5, kk = i & 31;
            float a0 = Scw[kk][4];
            a0 = fmaf(Sxz[tt + 0][kk], Scw[kk][0], a0);
            a0 = fmaf(Sxz[tt + 1][kk], Scw[kk][1], a0);
            a0 = fmaf(Sxz[tt + 2][kk], Scw[kk][2], a0);
            a0 = fmaf(Sxz[tt + 3][kk], Scw[kk][3], a0);
            float xv = a0 / (1.f + __expf(-a0));
            Xs[tt][kk] = xv;
            g_xi[(size_t)(tok0 + tt) * DINNER + k0 + kk] = xv;
        }
        __syncthreads();

#pragma unroll
        for (int kk = 0; kk < 32; kk++) {
            float w = Ws[tx][kk];
#pragma unroll
            for (int i = 0; i < 8; i++)
                acc[i] = fmaf(Xs[ty * 8 + i][kk], w, acc[i]);
        }
        __syncthreads();
    }
#pragma unroll
    for (int i = 0; i < 8; i++)
        g_dbcp[blockIdx.y][(size_t)(tok0 + ty * 8 + i) * 33 + tx] = acc[i];

    // last-block-done reduction over the 16 k-slices of this token block
    __threadfence();
    __syncthreads();
    if (tid == 0) sOld = atomicAdd(&g_cntx[blockIdx.x], 1);
    __syncthreads();
    if (sOld == 15) {
        __threadfence();
        const size_t base = (size_t)tok0 * 33;
        for (int i = tid; i < 64 * 33; i += 264) {
            float s = 0.f;
#pragma unroll
            for (int p = 0; p < 16; p++) s += g_dbcp[p][base + i];
            g_dbc[base + i] = s;
        }
        if (tid == 0) g_cntx[blockIdx.x] = 0;   // reset for next replay
    }
}

// ---------------------------------------------------------------------------
// Selective scan, 3-stage cp.async ring (prefetch distance 2 chunks):
// at iter c, group c is complete while group c+1 is still in flight, so each
// chunk's loads are covered by a FULL previous chunk of compute.
// Arithmetic identical to R14.
// ---------------------------------------------------------------------------
#define CH 32
#define CPB 8
#define PSTRIDE 17
#define NCHUNK (SEQL / CH)

__global__ void __launch_bounds__(128, 4)
scan_k(const float* __restrict__ A_log, const float* __restrict__ Dvec,
       const float* __restrict__ Wdt, const float* __restrict__ bdt) {
    __shared__ __align__(16) float  sDBC[3][CH * 33];
    __shared__ __align__(16) float  sXr [3][CH][8];
    __shared__ __align__(16) float  sZ  [3][CH][8];
    __shared__ __align__(16) float2 sDX [3][CH][8];   // (softplus(dt), xi)
    __shared__ float sP[CH][CPB * PSTRIDE];
    const int tid = threadIdx.x;              // 128
    const int dd = tid >> 4, n = tid & 15;
    const int q8 = tid & 7;
    const int b = blockIdx.y;
    const int d0 = blockIdx.x * CPB;

    const float a  = -__expf(A_log[(d0 + dd) * DSTATE + n]);
    const float wq = Wdt[d0 + q8];
    const float bq = bdt[d0 + q8];
    const float Dq = Dvec[d0 + q8];
    float h = 0.f;

    auto issue = [&](int c) {
        if (c >= NCHUNK) { asm volatile("cp.async.commit_group;"); return; }
        const int buf = c % 3;
        const int tok0 = b * SEQL + c * CH;
        const float* src = &g_dbc[(size_t)tok0 * 33];
#pragma unroll
        for (int j = 0; j < 3; j++) {
            int g = tid + j * 128;
            if (g < 264) cp_async16(&sDBC[buf][g * 4], src + g * 4);
        }
        if (tid < 64) {
            int token = tid >> 1, half = tid & 1;
            cp_async16(&sXr[buf][token][half * 4],
                       &g_xi[(size_t)(tok0 + token) * DINNER + d0 + half * 4]);
        } else {
            int t2 = tid - 64, token = t2 >> 1, half = t2 & 1;
            cp_async16(&sZ[buf][token][half * 4],
                       &g_xz[(size_t)(tok0 + token) * (2 * DINNER) + DINNER + d0 + half * 4]);
        }
        asm volatile("cp.async.commit_group;");
    };

    issue(0);
    issue(1);
    for (int c = 0; c < NCHUNK; c++) {
        const int buf = c % 3;
        const int tok0 = b * SEQL + c * CH;
        asm volatile("cp.async.wait_group 1;");   // group c done; c+1 may fly
        __syncthreads();                          // also protects buf (c+2)%3 reuse

        issue(c + 2);                             // full-chunk prefetch distance

#pragma unroll
        for (int j = 0; j < 2; j++) {
            int tt = (tid + j * 128) >> 3;
            float u = sDBC[buf][tt * 33] * wq + bq;
            float sp = (u > 20.f) ? u : log1pf(__expf(u));
            sDX[buf][tt][q8] = make_float2(sp, sXr[buf][tt][q8]);
        }
        __syncthreads();                          // sDX visible

        float dA[CH], bx[CH];
#pragma unroll
        for (int t = 0; t < CH; t++) {
            float2 dx = sDX[buf][t][dd];
            dA[t] = __expf(dx.x * a);
            bx[t] = (dx.x * sDBC[buf][t * 33 + 1 + n]) * dx.y;
        }
#pragma unroll
        for (int t = 0; t < CH; t++) {
            h = fmaf(dA[t], h, bx[t]);
            sP[t][dd * PSTRIDE + n] = h * sDBC[buf][t * 33 + 17 + n];
        }
        __syncthreads();                          // sP visible

#pragma unroll
        for (int j = 0; j < 2; j++) {
            int i = tid + j * 128;
            int tt = i >> 3;
            float s = 0.f;
#pragma unroll
            for (int k = 0; k < 16; k++) s += sP[tt][q8 * PSTRIDE + k];
            float xv = sXr[buf][tt][q8], zv = sZ[buf][tt][q8];
            float yv = (s + Dq * xv) * (zv / (1.f + __expf(-zv)));
            g_yh[(size_t)(tok0 + tt) * DINNER + d0 + q8] = __float2half_rn(yv);
        }
        // next-iter top barrier protects sP and ring-buffer reuse
    }
}

// ---------------------------------------------------------------------------
extern "C" void kernel_launch(void* const* d_in, const int* in_sizes, int n_in,
                              void* d_out, int out_size) {
    const float* x     = (const float*)d_in[0];
    const float* W_in  = (const float*)d_in[1];
    const float* convw = (const float*)d_in[2];
    const float* convb = (const float*)d_in[3];
    const float* W_x   = (const float*)d_in[4];
    const float* W_dt  = (const float*)d_in[5];
    const float* b_dt  = (const float*)d_in[6];
    const float* A_log = (const float*)d_in[7];
    const float* Dv    = (const float*)d_in[8];
    const float* W_out = (const float*)d_in[9];
    float* out = (float*)d_out;

    float *xz;
    __half *xh, *wh, *woh, *yh;
    cudaGetSymbolAddress((void**)&xz,  g_xz);
    cudaGetSymbolAddress((void**)&xh,  g_xh);
    cudaGetSymbolAddress((void**)&wh,  g_wh);
    cudaGetSymbolAddress((void**)&woh, g_woh);
    cudaGetSymbolAddress((void**)&yh,  g_yh);

    cudaFuncSetAttribute(h_gemm_nt, cudaFuncAttributeMaxDynamicSharedMemorySize, GEMM_SMEM);

    // 1) convert x + W_in to fp16
    cvt_xw_k<<<(N4_X + N4_WI + 255) / 256, 256>>>(x, W_in);

    // 2) xz = x @ W_in^T   [4096 x 4096], K=1024
    h_gemm_nt<<<dim3(4096 / BN, TOKENS / BM), 256, GEMM_SMEM>>>(xh, wh, xz, TOKENS, 4096, DMODEL);

    // 3) fused conv+silu + x_dbl partials + in-kernel reduce
    xdbl_conv_k<<<dim3(TOKENS / 64, 16), dim3(33, 8)>>>(W_x, convw, convb);

    // 4) selective scan -> g_yh (half)   [profiled slot]
    scan_k<<<dim3(DINNER / CPB, 2), 128>>>(A_log, Dv, W_dt, b_dt);

    // 5) convert W_out (only needed by GEMM2)
    cvt_wo_k<<<(N4_WO + 255) / 256, 256>>>(W_out);

    // 6) out = y @ W_out^T   [4096 x 1024], K=2048
    h_gemm_nt<<<dim3(DMODEL / BN, TOKENS / BM), 256, GEMM_SMEM>>>(yh, woh, out, TOKENS, DMODEL, DINNER);
}